// round 4
// baseline (speedup 1.0000x reference)
#include <cuda_runtime.h>

#define Hh 128
#define Ww 128
#define Cc 64
#define PAD 3
#define HP 134
#define WP 134
#define WS 7
#define SST 145   // padded S row stride (odd*  -> conflict-free 9-strided stores)
#define QKW 145   // padded Q/K width in smem

// ---------------- scratch (device globals; no allocation allowed) ----------
__device__ float g_qpad[Cc * HP * WP];   // padded q  (C, HP, WP)
__device__ float g_kpad[Cc * HP * WP];
__device__ float g_vpad[Cc * HP * WP];
__device__ float g_T[HP * Hh * Ww];      // T[r][w][k] = sum_pj S_r[w+pj, k+pj]
__device__ float g_attn[Hh * Ww * Ww];   // attn[h][w][k] (post-softmax)
__device__ float g_hs[Cc * HP * Ww];     // horizontal 7-box of vpad
__device__ float g_vsum[Cc * Hh * Ww];   // 7x7 box sum of vpad

// ---------------- kernel 0: zero the 3-wide halo of padded buffers ---------
// Interior is fully overwritten by k_qkv each replay; only borders need zeros.
__global__ void k_zero() {
    const int n = Cc * HP * WP;
    for (int i = blockIdx.x * blockDim.x + threadIdx.x; i < n;
         i += gridDim.x * blockDim.x) {
        const int rw = i % (HP * WP);
        const int r = rw / WP, w = rw % WP;
        if (r < PAD || r >= HP - PAD || w < PAD || w >= WP - PAD) {
            g_qpad[i] = 0.f; g_kpad[i] = 0.f; g_vpad[i] = 0.f;
        }
    }
}

// ---------------- kernel 1: q/k/v = 1x1 conv, written into padded bufs -----
// grid 512, block 256. Each warp: 32 consecutive pixels, 8 output channels.
__global__ void k_qkv(const float* __restrict__ x,
                      const float* __restrict__ Wq, const float* __restrict__ bq,
                      const float* __restrict__ Wk, const float* __restrict__ bk,
                      const float* __restrict__ Wv, const float* __restrict__ bv) {
    __shared__ float sW[3 * Cc * Cc];   // 48 KB exactly
    float* sWq = sW;
    float* sWk = sW + Cc * Cc;
    float* sWv = sW + 2 * Cc * Cc;
    for (int i = threadIdx.x; i < Cc * Cc; i += blockDim.x) {
        sWq[i] = Wq[i]; sWk[i] = Wk[i]; sWv[i] = Wv[i];
    }
    __syncthreads();

    const int base = blockIdx.x * 32;              // 32 pixels per block
    const int p    = threadIdx.x & 31;             // lane -> pixel (coalesced)
    const int og   = (threadIdx.x >> 5) * 8;       // warp -> 8 out channels
    const int s    = base + p;
    const int h = s >> 7, w = s & 127;
    const int po = (h + PAD) * WP + (w + PAD);

    float xv[Cc];
#pragma unroll
    for (int c = 0; c < Cc; c++) xv[c] = x[c * (Hh * Ww) + s];

#pragma unroll
    for (int oo = 0; oo < 8; oo++) {
        const int o = og + oo;
        float aq = __ldg(&bq[o]), ak = __ldg(&bk[o]), av = __ldg(&bv[o]);
#pragma unroll
        for (int c = 0; c < Cc; c++) {
            const float xc = xv[c];
            aq += sWq[o * Cc + c] * xc;
            ak += sWk[o * Cc + c] * xc;
            av += sWv[o * Cc + c] * xc;
        }
        g_qpad[o * HP * WP + po] = aq;
        g_kpad[o * HP * WP + po] = ak;
        g_vpad[o * HP * WP + po] = av;
    }
}

// ---------------- kernel 2: per-row Gram matrix + diagonal 7-band sum ------
// grid = HP (one CTA per padded row), block 256.
// 9x9 register tiles -> 16x16 = 256 tiles: every thread active, exactly
// 2 warps per SMSP (perfect FMA-pipe balance). Odd stride 145 keeps both the
// 9-strided loads and the tile stores bank-conflict-free.
__global__ void __launch_bounds__(256, 1) k_gram() {
    extern __shared__ float sm[];
    float* sQ = sm;                      // [64][145]
    float* sK = sm + Cc * QKW;           // [64][145]
    float* sS = sm + 2 * Cc * QKW;       // [145][145] (rows 0..143 used)
    const int r = blockIdx.x;
    const int tid = threadIdx.x;

    for (int i = tid; i < Cc * QKW; i += 256) {
        const int c = i / QKW, w = i % QKW;
        float qv = 0.f, kv = 0.f;
        if (w < WP) {
            qv = g_qpad[c * HP * WP + r * WP + w];
            kv = g_kpad[c * HP * WP + r * WP + w];
        }
        sQ[i] = qv; sK[i] = kv;
    }
    __syncthreads();

    // S[w'][k'] = sum_c Q[c][w'] K[c][k'] ; 9x9 tiles, 144x144 coverage
    {
        const int wt = tid & 15, kt = tid >> 4;
        const int w0 = wt * 9, k0 = kt * 9;
        float acc[9][9];
#pragma unroll
        for (int i = 0; i < 9; i++)
#pragma unroll
            for (int j = 0; j < 9; j++) acc[i][j] = 0.f;

#pragma unroll 2
        for (int c = 0; c < Cc; c++) {
            float q[9], kk[9];
#pragma unroll
            for (int i = 0; i < 9; i++) q[i] = sQ[c * QKW + w0 + i];
#pragma unroll
            for (int j = 0; j < 9; j++) kk[j] = sK[c * QKW + k0 + j];
#pragma unroll
            for (int i = 0; i < 9; i++)
#pragma unroll
                for (int j = 0; j < 9; j++) acc[i][j] += q[i] * kk[j];
        }
#pragma unroll
        for (int i = 0; i < 9; i++)
#pragma unroll
            for (int j = 0; j < 9; j++)
                sS[(w0 + i) * SST + k0 + j] = acc[i][j];
    }
    __syncthreads();

    // T[w][k] = sum_{pj<7} S[w+pj][k+pj]
    for (int o = tid; o < Hh * Ww; o += 256) {
        const int w = o >> 7, k = o & 127;
        float s = 0.f;
#pragma unroll
        for (int p = 0; p < WS; p++) s += sS[(w + p) * SST + (k + p)];
        g_T[r * (Hh * Ww) + o] = s;
    }
}

// ---------------- kernel 3: logits = sum_pi T[h+pi], softmax over k --------
// One warp per (h,w); 4 k-values per lane via float4. grid 2048, block 256.
__global__ void k_softmax() {
    const int warp = (blockIdx.x * blockDim.x + threadIdx.x) >> 5;  // 0..16383
    const int lane = threadIdx.x & 31;
    const int h = warp >> 7, w = warp & 127;

    float4 lg = make_float4(0.f, 0.f, 0.f, 0.f);
#pragma unroll
    for (int p = 0; p < WS; p++) {
        const float4 t = *(const float4*)&g_T[(h + p) * (Hh * Ww) + w * Ww + lane * 4];
        lg.x += t.x; lg.y += t.y; lg.z += t.z; lg.w += t.w;
    }

    float m = fmaxf(fmaxf(lg.x, lg.y), fmaxf(lg.z, lg.w));
#pragma unroll
    for (int off = 16; off; off >>= 1)
        m = fmaxf(m, __shfl_xor_sync(0xffffffffu, m, off));

    float4 e;
    e.x = expf(lg.x - m); e.y = expf(lg.y - m);
    e.z = expf(lg.z - m); e.w = expf(lg.w - m);
    float s = e.x + e.y + e.z + e.w;
#pragma unroll
    for (int off = 16; off; off >>= 1)
        s += __shfl_xor_sync(0xffffffffu, s, off);

    const float inv = 1.0f / s;
    e.x *= inv; e.y *= inv; e.z *= inv; e.w *= inv;
    *(float4*)&g_attn[warp * Ww + lane * 4] = e;
}

// ---------------- kernel 4a: horizontal 7-box of vpad ----------------------
__global__ void k_hbox() {
    const int bid = blockIdx.x;          // c*HP + r
    const int k = threadIdx.x;           // 0..127
    const float* row = &g_vpad[bid * WP];
    float s = 0.f;
#pragma unroll
    for (int p = 0; p < WS; p++) s += row[k + p];
    g_hs[bid * Ww + k] = s;
}

// ---------------- kernel 4b: vertical 7-box -> vsum[c][h][k] ---------------
__global__ void k_vbox() {
    const int bid = blockIdx.x;          // c*H + h
    const int c = bid >> 7, h = bid & 127;
    const int k = threadIdx.x;
    float s = 0.f;
#pragma unroll
    for (int p = 0; p < WS; p++) s += g_hs[(c * HP + h + p) * Ww + k];
    g_vsum[bid * Ww + k] = s;
}

// ---------------- kernel 5: out[c,h,w] = sum_k attn[h,w,k] * vsum[c,h,k] ---
// grid = H, block 256, dyn smem 99328 B.
// Warp ww owns c-block ww*8..+7 (sV reads broadcast); lane l owns
// w in {l, l+32, l+64, l+96} (sA reads conflict-free for any stride).
__global__ void k_out(float* __restrict__ out) {
    extern __shared__ float sm[];
    float* sA = sm;                 // attn transposed: [k][w], stride 129
    float* sV = sm + 128 * 129;     // vsum transposed: [k][c], stride 65
    const int h = blockIdx.x;
    const int tid = threadIdx.x;

    for (int i = tid; i < Hh * Ww; i += 256) {          // 16384
        const int w = i >> 7, k = i & 127;              // i = w*128 + k
        sA[k * 129 + w] = g_attn[h * (Hh * Ww) + i];    // STS stride-129: conflict-free
    }
    for (int i = tid; i < Cc * Ww; i += 256) {          // 8192
        const int c = i >> 7, k = i & 127;
        sV[k * 65 + c] = g_vsum[(c * Hh + h) * Ww + k]; // STS stride-65: conflict-free
    }
    __syncthreads();

    const int lane = tid & 31;
    const int ww = tid >> 5;            // 0..7
    const int c0 = ww * 8;
    float acc[8][4];
#pragma unroll
    for (int i = 0; i < 8; i++)
#pragma unroll
        for (int j = 0; j < 4; j++) acc[i][j] = 0.f;

    for (int k = 0; k < 128; k++) {
        float av[4];
#pragma unroll
        for (int j = 0; j < 4; j++) av[j] = sA[k * 129 + lane + 32 * j];
#pragma unroll
        for (int i = 0; i < 8; i++) {
            const float vv = sV[k * 65 + c0 + i];       // warp-uniform: broadcast
#pragma unroll
            for (int j = 0; j < 4; j++) acc[i][j] += vv * av[j];
        }
    }
#pragma unroll
    for (int i = 0; i < 8; i++)
#pragma unroll
        for (int j = 0; j < 4; j++)
            out[(c0 + i) * (Hh * Ww) + h * Ww + lane + 32 * j] = acc[i][j];
}

// ---------------------------------------------------------------------------
extern "C" void kernel_launch(void* const* d_in, const int* in_sizes, int n_in,
                              void* d_out, int out_size) {
    const float* x  = (const float*)d_in[0];
    const float* Wq = (const float*)d_in[1];
    const float* bq = (const float*)d_in[2];
    const float* Wk = (const float*)d_in[3];
    const float* bk = (const float*)d_in[4];
    const float* Wv = (const float*)d_in[5];
    const float* bv = (const float*)d_in[6];
    float* out = (float*)d_out;

    // Opt-in to >48KB dynamic smem (not a stream op; safe under graph capture).
    const int smemB = (2 * Cc * QKW + SST * SST) * 4;   // 158340
    const int smemE = (128 * 129 + 128 * 65) * 4;       // 99328
    cudaFuncSetAttribute(k_gram, cudaFuncAttributeMaxDynamicSharedMemorySize, smemB);
    cudaFuncSetAttribute(k_out,  cudaFuncAttributeMaxDynamicSharedMemorySize, smemE);

    k_zero<<<256, 256>>>();
    k_qkv<<<(Hh * Ww) / 32, 256>>>(x, Wq, bq, Wk, bk, Wv, bv);
    k_gram<<<HP, 256, smemB>>>();
    k_softmax<<<(Hh * Ww) / 8, 256>>>();
    k_hbox<<<Cc * HP, Ww>>>();
    k_vbox<<<Cc * Hh, Ww>>>();
    k_out<<<Hh, 256, smemE>>>(out);
}